// round 13
// baseline (speedup 1.0000x reference)
#include <cuda_runtime.h>
#include <math.h>
#include <stdint.h>

#define BATCH 2
#define SEQ   2048
#define EMB   1024
#define NH    16
#define HD    64
#define NTOK  (BATCH*SEQ)   // 4096

// Scratch (allocation-free).
static __device__ float g_x[(size_t)NTOK * EMB];            // tf32-rounded x
static __device__ float g_qkv[(size_t)NTOK * 3 * EMB];      // QKV projections
static __device__ float g_attn[(size_t)NTOK * EMB];         // attention output (tf32 bits)
static __device__ float g_w_inT[(size_t)3 * EMB * EMB];     // w_in^T  (tf32 bits)
static __device__ float g_w_outT[(size_t)EMB * EMB];        // w_out^T (tf32 bits)

// ===========================================================================
// PTX helpers (sm_80-baseline: mma.sync tf32, ldmatrix, cp.async)
// ===========================================================================
__device__ __forceinline__ uint32_t smem_u32(const void* p) {
    uint32_t a;
    asm("{ .reg .u64 t; cvta.to.shared.u64 t, %1; cvt.u32.u64 %0, t; }"
        : "=r"(a) : "l"(p));
    return a;
}
__device__ __forceinline__ uint32_t f2tf32(float x) {
    uint32_t u;
    asm("cvt.rna.tf32.f32 %0, %1;" : "=r"(u) : "f"(x));
    return u;
}
__device__ __forceinline__ void ldsm_x4(uint32_t* r, uint32_t addr) {
    asm volatile("ldmatrix.sync.aligned.m8n8.x4.shared.b16 {%0,%1,%2,%3}, [%4];"
                 : "=r"(r[0]), "=r"(r[1]), "=r"(r[2]), "=r"(r[3]) : "r"(addr));
}
__device__ __forceinline__ void ldsm_x2(uint32_t* r, uint32_t addr) {
    asm volatile("ldmatrix.sync.aligned.m8n8.x2.shared.b16 {%0,%1}, [%2];"
                 : "=r"(r[0]), "=r"(r[1]) : "r"(addr));
}
__device__ __forceinline__ void mma_tf32(float* c, const uint32_t* a, const uint32_t* b) {
    asm volatile(
        "mma.sync.aligned.m16n8k8.row.col.f32.tf32.tf32.f32 "
        "{%0,%1,%2,%3}, {%4,%5,%6,%7}, {%8,%9}, {%0,%1,%2,%3};"
        : "+f"(c[0]), "+f"(c[1]), "+f"(c[2]), "+f"(c[3])
        : "r"(a[0]), "r"(a[1]), "r"(a[2]), "r"(a[3]), "r"(b[0]), "r"(b[1]));
}
__device__ __forceinline__ void cp_async16(uint32_t dst, const void* src) {
    asm volatile("cp.async.cg.shared.global [%0], [%1], 16;" :: "r"(dst), "l"(src));
}
#define CP_COMMIT() asm volatile("cp.async.commit_group;" ::: "memory")
#define CP_WAIT(n)  asm volatile("cp.async.wait_group %0;" :: "n"(n) : "memory")

// ===========================================================================
// Pre-passes: tf32 rounding + transposed-rounded weights
// ===========================================================================
__global__ void round_tf32_kernel(const float* __restrict__ in, float* __restrict__ out)
{
    int i = (blockIdx.x * blockDim.x + threadIdx.x) * 4;
    float4 v = *(const float4*)(in + i);
    uint4 t = make_uint4(f2tf32(v.x), f2tf32(v.y), f2tf32(v.z), f2tf32(v.w));
    *(uint4*)(out + i) = t;
}

__global__ void transpose_round_kernel(const float* __restrict__ in, float* __restrict__ out,
                                       int R, int C)
{
    __shared__ float t[32][33];
    int c0 = blockIdx.x * 32, r0 = blockIdx.y * 32;
    int x = threadIdx.x, y = threadIdx.y;   // block (32,8)
#pragma unroll
    for (int i = 0; i < 32; i += 8)
        t[y + i][x] = in[(size_t)(r0 + y + i) * C + c0 + x];
    __syncthreads();
#pragma unroll
    for (int i = 0; i < 32; i += 8)
        out[(size_t)(c0 + y + i) * R + r0 + x] = __uint_as_float(f2tf32(t[x][y + i]));
}

// ===========================================================================
// TF32 mma GEMM + bias, cp.async 3-stage pipeline.
// C[M,N] = A[M,K] @ Bt[N,K]^T + bias[N]. A, Bt pre-rounded to tf32 bits.
// CTA 128x128x32, 256 threads, 8 warps (2x4), warp tile 64x32.
// Dynamic smem: stage s at s*32768 (A 16KB | B 16KB), 3 stages = 96KB.
// ===========================================================================
#define GEMM_SMEM_BYTES (3 * 32768)

__global__ __launch_bounds__(256, 2)
void gemm_mma(const float* __restrict__ A, const float* __restrict__ Bt,
              const float* __restrict__ bias, float* __restrict__ C,
              int M, int N, int K)
{
    extern __shared__ char gsm[];
    const uint32_t sbase = smem_u32(gsm);

    const int tid  = threadIdx.x;
    const int wid  = tid >> 5, lane = tid & 31;
    const int wm   = wid >> 2;      // 0..1
    const int wn   = wid & 3;       // 0..3
    const int mBase = blockIdx.y * 128;
    const int nBase = blockIdx.x * 128;

    const int a_tile = lane >> 3, a_r = lane & 7;
    const int b_tile = (lane >> 3) & 1, b_r = lane & 7;

    const float* Ag = A  + (size_t)mBase * K;
    const float* Bg = Bt + (size_t)nBase * K;

    const int ld_row = tid >> 3, ld_kq = tid & 7;   // 32 rows per pass, 4 passes

    auto issue = [&](int stage, int k0) {
#pragma unroll
        for (int it = 0; it < 4; it++) {
            int row = ld_row + it * 32;
            uint32_t off = row * 128 + ld_kq * 16;
            off ^= (off >> 3) & 0x70;
            cp_async16(sbase + stage * 32768 + off,
                       Ag + (size_t)row * K + k0 + ld_kq * 4);
            cp_async16(sbase + stage * 32768 + 16384 + off,
                       Bg + (size_t)row * K + k0 + ld_kq * 4);
        }
        CP_COMMIT();
    };

    float c[4][4][4];
#pragma unroll
    for (int mi = 0; mi < 4; mi++)
#pragma unroll
        for (int ni = 0; ni < 4; ni++)
#pragma unroll
            for (int j = 0; j < 4; j++) c[mi][ni][j] = 0.f;

    const int niter = K / 32;
    issue(0, 0);
    issue(1, 32);

    for (int i = 0; i < niter; i++) {
        if (i + 1 < niter) { CP_WAIT(1); } else { CP_WAIT(0); }
        __syncthreads();
        if (i + 2 < niter) {
            int s = (i + 2) % 3;
            issue(s, (i + 2) * 32);
        }

        const uint32_t as_b = sbase + (i % 3) * 32768;
        const uint32_t bs_b = as_b + 16384;

#pragma unroll
        for (int kk = 0; kk < 32; kk += 8) {
            uint32_t af[4][4], bf[4][2];
#pragma unroll
            for (int mi = 0; mi < 4; mi++) {
                int m = wm * 64 + mi * 16 + a_r + (a_tile & 1) * 8;
                int k = kk + (a_tile >> 1) * 4;
                uint32_t off = m * 128 + k * 4;
                off ^= (off >> 3) & 0x70;
                ldsm_x4(af[mi], as_b + off);
            }
#pragma unroll
            for (int ni = 0; ni < 4; ni++) {
                int n = wn * 32 + ni * 8 + b_r;
                int k = kk + b_tile * 4;
                uint32_t off = n * 128 + k * 4;
                off ^= (off >> 3) & 0x70;
                ldsm_x2(bf[ni], bs_b + off);
            }
#pragma unroll
            for (int mi = 0; mi < 4; mi++)
#pragma unroll
                for (int ni = 0; ni < 4; ni++)
                    mma_tf32(c[mi][ni], af[mi], bf[ni]);
        }
    }

    __syncthreads();
    const int r = lane >> 2, q = lane & 3;
#pragma unroll
    for (int mi = 0; mi < 4; mi++) {
        int m0 = mBase + wm * 64 + mi * 16 + r;
#pragma unroll
        for (int ni = 0; ni < 4; ni++) {
            int n0 = nBase + wn * 32 + ni * 8 + q * 2;
            float2 bv = *(const float2*)(bias + n0);
            float2 o0, o1;
            o0.x = c[mi][ni][0] + bv.x; o0.y = c[mi][ni][1] + bv.y;
            o1.x = c[mi][ni][2] + bv.x; o1.y = c[mi][ni][3] + bv.y;
            *(float2*)(C + (size_t)m0 * N + n0)       = o0;
            *(float2*)(C + (size_t)(m0 + 8) * N + n0) = o1;
        }
    }
}

// ===========================================================================
// Flash attention, TF32 mma.sync. One CTA = 128 queries x (batch, head).
// 256 threads, 8 warps; warp w owns query rows w*16..w*16+15 (1 m16 tile).
// KV tiles of 64, register double-buffered: next tile's K/V prefetched into
// registers (4+4 float4 per thread) during current tile's compute.
// smem rows stride AST=68 (272B): ldmatrix row step = 17 16B-groups == 1 mod 8
// -> conflict-free.  smem: Qs 128x68 | Ks 64x68 | Vt 64x68 | Ps 128x68.
//
// B-fragment gather via one ldsm_x4 over a 16(n) x 8(k) region:
//   tmp[0]=n[0:8),k[0:4)  tmp[1]=n[0:8),k[4:8)  tmp[2]=n[8:16),k[0:4)  tmp[3]=n[8:16),k[4:8)
// -> bf[2np]={tmp0,tmp1}, bf[2np+1]={tmp2,tmp3}
// ===========================================================================
#define AST 68
#define ATTN_SMEM_BYTES ((128*AST + 64*AST + 64*AST + 128*AST) * 4)

__global__ __launch_bounds__(256, 2)
void mha_mma_kernel(const float* __restrict__ qkv, float* __restrict__ out)
{
    extern __shared__ float smf[];
    float* Qs = smf;                 // [m][d]
    float* Ks = Qs + 128 * AST;      // [kv][d]
    float* Vt = Ks + 64 * AST;       // [d][kv]
    float* Ps = Vt + 64 * AST;       // [m][kv]
    const uint32_t qs_b = smem_u32(Qs), ks_b = smem_u32(Ks);
    const uint32_t vt_b = smem_u32(Vt), ps_b = smem_u32(Ps);

    const int tid  = threadIdx.x;
    const int warp = tid >> 5, lane = tid & 31;
    const int r = lane >> 2, q = lane & 3;
    const int a_tile = lane >> 3, a_r = lane & 7;

    const int h  = blockIdx.y & (NH - 1);
    const int b  = blockIdx.y >> 4;
    const int q0 = blockIdx.x * 128;
    const size_t rs = 3 * EMB;

    const float* Qg = qkv + ((size_t)b * SEQ + q0) * rs + h * HD;
    const float* Kg = qkv + (size_t)b * SEQ * rs + EMB + h * HD;
    const float* Vg = qkv + (size_t)b * SEQ * rs + 2 * EMB + h * HD;

    // Load Q tile (128 x 64), scale by 1/8, round to tf32.
#pragma unroll
    for (int it = 0; it < 8; it++) {
        int f = tid + it * 256;
        int m = f >> 4, c4 = f & 15;
        float4 v = *(const float4*)(Qg + (size_t)m * rs + c4 * 4);
        uint4 t = make_uint4(f2tf32(v.x * 0.125f), f2tf32(v.y * 0.125f),
                             f2tf32(v.z * 0.125f), f2tf32(v.w * 0.125f));
        *(uint4*)(Qs + m * AST + c4 * 4) = t;
    }

    float o[8][4];
#pragma unroll
    for (int ni = 0; ni < 8; ni++)
#pragma unroll
        for (int j = 0; j < 4; j++) o[ni][j] = 0.f;
    float m_st[2] = {-1e30f, -1e30f};
    float l_st[2] = {0.f, 0.f};

    // K/V prefetch mapping: f = tid + j*256 -> kv = (tid>>4) + j*16, c4 = tid&15.
    const int pf_kv0 = tid >> 4;    // 0..15
    const int pf_c4  = tid & 15;    // 0..15

    float4 kreg[4], vreg[4];
#pragma unroll
    for (int j = 0; j < 4; j++) {
        int kv = pf_kv0 + j * 16;
        kreg[j] = *(const float4*)(Kg + (size_t)kv * rs + pf_c4 * 4);
        vreg[j] = *(const float4*)(Vg + (size_t)kv * rs + pf_c4 * 4);
    }

    for (int ti = 0; ti < SEQ / 64; ti++) {
        // Store prefetched K (rounded, [kv][d]) and V (rounded, transposed [d][kv]).
#pragma unroll
        for (int j = 0; j < 4; j++) {
            int kv = pf_kv0 + j * 16;
            uint4 tk = make_uint4(f2tf32(kreg[j].x), f2tf32(kreg[j].y),
                                  f2tf32(kreg[j].z), f2tf32(kreg[j].w));
            *(uint4*)(Ks + kv * AST + pf_c4 * 4) = tk;
            Vt[(pf_c4 * 4 + 0) * AST + kv] = __uint_as_float(f2tf32(vreg[j].x));
            Vt[(pf_c4 * 4 + 1) * AST + kv] = __uint_as_float(f2tf32(vreg[j].y));
            Vt[(pf_c4 * 4 + 2) * AST + kv] = __uint_as_float(f2tf32(vreg[j].z));
            Vt[(pf_c4 * 4 + 3) * AST + kv] = __uint_as_float(f2tf32(vreg[j].w));
        }
        __syncthreads();

        // Prefetch next tile into registers (latency hidden by compute below).
        if (ti + 1 < SEQ / 64) {
            const float* Kn = Kg + (size_t)(ti + 1) * 64 * rs;
            const float* Vn = Vg + (size_t)(ti + 1) * 64 * rs;
#pragma unroll
            for (int j = 0; j < 4; j++) {
                int kv = pf_kv0 + j * 16;
                kreg[j] = *(const float4*)(Kn + (size_t)kv * rs + pf_c4 * 4);
                vreg[j] = *(const float4*)(Vn + (size_t)kv * rs + pf_c4 * 4);
            }
        }

        // ---- S = Q @ K^T  (warp: 16 x 64) ----
        float s[8][4];
#pragma unroll
        for (int ni = 0; ni < 8; ni++)
#pragma unroll
            for (int j = 0; j < 4; j++) s[ni][j] = 0.f;

#pragma unroll
        for (int kk = 0; kk < 64; kk += 8) {
            uint32_t af[4], bf[8][2];
            {
                int m = warp * 16 + (a_tile & 1) * 8 + a_r;
                int k = kk + (a_tile >> 1) * 4;
                ldsm_x4(af, qs_b + (m * AST + k) * 4);
            }
#pragma unroll
            for (int np = 0; np < 4; np++) {
                int n = np * 16 + (a_tile >> 1) * 8 + a_r;
                int k = kk + (a_tile & 1) * 4;
                uint32_t tmp[4];
                ldsm_x4(tmp, ks_b + (n * AST + k) * 4);
                bf[np * 2][0]     = tmp[0]; bf[np * 2][1]     = tmp[1];
                bf[np * 2 + 1][0] = tmp[2]; bf[np * 2 + 1][1] = tmp[3];
            }
#pragma unroll
            for (int ni = 0; ni < 8; ni++)
                mma_tf32(s[ni], af, bf[ni]);
        }

        // ---- online softmax (rows live in 4-lane groups) ----
#pragma unroll
        for (int hh = 0; hh < 2; hh++) {
            float tmax = -1e30f;
#pragma unroll
            for (int ni = 0; ni < 8; ni++) {
                tmax = fmaxf(tmax, s[ni][hh * 2]);
                tmax = fmaxf(tmax, s[ni][hh * 2 + 1]);
            }
            tmax = fmaxf(tmax, __shfl_xor_sync(0xffffffffu, tmax, 1));
            tmax = fmaxf(tmax, __shfl_xor_sync(0xffffffffu, tmax, 2));
            float mold = m_st[hh];
            float mnew = fmaxf(mold, tmax);
            float alpha = __expf(mold - mnew);
            float sum = 0.f;
#pragma unroll
            for (int ni = 0; ni < 8; ni++) {
                float p0 = __expf(s[ni][hh * 2]     - mnew);
                float p1 = __expf(s[ni][hh * 2 + 1] - mnew);
                s[ni][hh * 2] = p0; s[ni][hh * 2 + 1] = p1;
                sum += p0 + p1;
            }
            sum += __shfl_xor_sync(0xffffffffu, sum, 1);
            sum += __shfl_xor_sync(0xffffffffu, sum, 2);
            l_st[hh] = l_st[hh] * alpha + sum;
            m_st[hh] = mnew;
#pragma unroll
            for (int ni = 0; ni < 8; ni++) {
                o[ni][hh * 2]     *= alpha;
                o[ni][hh * 2 + 1] *= alpha;
            }
        }

        // ---- store P (tf32 bits) ----
        {
            int m0 = warp * 16 + r;
#pragma unroll
            for (int ni = 0; ni < 8; ni++) {
                int col = ni * 8 + q * 2;
                uint2 p0 = make_uint2(f2tf32(s[ni][0]), f2tf32(s[ni][1]));
                uint2 p1 = make_uint2(f2tf32(s[ni][2]), f2tf32(s[ni][3]));
                *(uint2*)(Ps + m0 * AST + col)       = p0;
                *(uint2*)(Ps + (m0 + 8) * AST + col) = p1;
            }
        }
        __syncthreads();

        // ---- O += P @ V  (A from Ps, B from Vt) ----
#pragma unroll
        for (int kk = 0; kk < 64; kk += 8) {
            uint32_t af[4], bf[8][2];
            {
                int m = warp * 16 + (a_tile & 1) * 8 + a_r;
                int k = kk + (a_tile >> 1) * 4;
                ldsm_x4(af, ps_b + (m * AST + k) * 4);
            }
#pragma unroll
            for (int np = 0; np < 4; np++) {
                int n = np * 16 + (a_tile >> 1) * 8 + a_r;
                int k = kk + (a_tile & 1) * 4;
                uint32_t tmp[4];
                ldsm_x4(tmp, vt_b + (n * AST + k) * 4);
                bf[np * 2][0]     = tmp[0]; bf[np * 2][1]     = tmp[1];
                bf[np * 2 + 1][0] = tmp[2]; bf[np * 2 + 1][1] = tmp[3];
            }
#pragma unroll
            for (int ni = 0; ni < 8; ni++)
                mma_tf32(o[ni], af, bf[ni]);
        }
        __syncthreads();
    }

    // Epilogue: O / l, round to tf32 bits (feeds GEMM2), write out.
    const size_t orow = (size_t)b * SEQ + q0;
    {
        float inv0 = 1.0f / l_st[0];
        float inv1 = 1.0f / l_st[1];
        int m0 = warp * 16 + r;
#pragma unroll
        for (int ni = 0; ni < 8; ni++) {
            int col = h * HD + ni * 8 + q * 2;
            uint2 v0 = make_uint2(f2tf32(o[ni][0] * inv0), f2tf32(o[ni][1] * inv0));
            uint2 v1 = make_uint2(f2tf32(o[ni][2] * inv1), f2tf32(o[ni][3] * inv1));
            *(uint2*)(out + (orow + m0) * EMB + col)     = v0;
            *(uint2*)(out + (orow + m0 + 8) * EMB + col) = v1;
        }
    }
}

// ===========================================================================
extern "C" void kernel_launch(void* const* d_in, const int* in_sizes, int n_in,
                              void* d_out, int out_size)
{
    const float* x     = (const float*)d_in[0];
    const float* w_in  = (const float*)d_in[1];
    const float* b_in  = (const float*)d_in[2];
    const float* w_out = (const float*)d_in[3];
    const float* b_out = (const float*)d_in[4];
    float* out = (float*)d_out;

    static float* x_buf    = nullptr;
    static float* qkv_buf  = nullptr;
    static float* attn_buf = nullptr;
    static float* w_inT    = nullptr;
    static float* w_outT   = nullptr;
    static bool   init     = false;
    if (!init) {
        cudaGetSymbolAddress((void**)&x_buf,    g_x);
        cudaGetSymbolAddress((void**)&qkv_buf,  g_qkv);
        cudaGetSymbolAddress((void**)&attn_buf, g_attn);
        cudaGetSymbolAddress((void**)&w_inT,    g_w_inT);
        cudaGetSymbolAddress((void**)&w_outT,   g_w_outT);
        cudaFuncSetAttribute(mha_mma_kernel,
                             cudaFuncAttributeMaxDynamicSharedMemorySize,
                             ATTN_SMEM_BYTES);
        cudaFuncSetAttribute(gemm_mma,
                             cudaFuncAttributeMaxDynamicSharedMemorySize,
                             GEMM_SMEM_BYTES);
        init = true;
    }

    // 0) Pre-round x; transpose+round weights to K-major tf32 bits.
    round_tf32_kernel<<<NTOK * EMB / 1024, 256>>>(x, x_buf);
    transpose_round_kernel<<<dim3(3 * EMB / 32, EMB / 32), dim3(32, 8)>>>(w_in,  w_inT,  EMB, 3 * EMB);
    transpose_round_kernel<<<dim3(EMB / 32,     EMB / 32), dim3(32, 8)>>>(w_out, w_outT, EMB, EMB);

    // 1) QKV projection: [4096,1024] @ [1024,3072] + b_in   (tf32 mma, 3-stage)
    gemm_mma<<<dim3(3 * EMB / 128, NTOK / 128), 256, GEMM_SMEM_BYTES>>>(
        x_buf, w_inT, b_in, qkv_buf, NTOK, 3 * EMB, EMB);

    // 2) Attention per (batch, head), 128-query tiles (tf32 mma flash, 8 warps)
    mha_mma_kernel<<<dim3(SEQ / 128, BATCH * NH), 256, ATTN_SMEM_BYTES>>>(
        qkv_buf, attn_buf);

    // 3) Output projection: [4096,1024] @ [1024,1024] + b_out  (tf32 mma, 3-stage)
    gemm_mma<<<dim3(EMB / 128, NTOK / 128), 256, GEMM_SMEM_BYTES>>>(
        attn_buf, w_outT, b_out, out, NTOK, EMB, EMB);
}